// round 8
// baseline (speedup 1.0000x reference)
#include <cuda_runtime.h>
#include <cuda_bf16.h>
#include <cstdint>

#define OPT 64
#define DIN 128
#define DOUT 128
#define TILE_M 128
#define MAX_B 16384
#define HBLK 16
#define MAX_TILES (MAX_B / TILE_M + OPT)      // 192

// ---- scratch (device allocation banned) ----
__device__ int g_blockhist[HBLK][OPT];
__device__ int g_blockbase[HBLK][OPT];
__device__ int g_expert_end[OPT];
__device__ int g_rowids[MAX_B];
__device__ int g_ntiles;
__device__ int g_tile_e[MAX_TILES];
__device__ int g_tile_m0[MAX_TILES];

// ---------------- Prelude: counting sort by expert (smem atomics only) ----------------

__global__ void hist_kernel(const int* __restrict__ idx, int B) {
    __shared__ int h[OPT];
    int t = threadIdx.x;
    if (t < OPT) h[t] = 0;
    __syncthreads();
    int i4 = blockIdx.x * 256 + t;
    if (i4 * 4 + 3 < B) {
        int4 v = ((const int4*)idx)[i4];
        if (v.x >= 0 && v.x < OPT) atomicAdd(&h[v.x], 1);
        if (v.y >= 0 && v.y < OPT) atomicAdd(&h[v.y], 1);
        if (v.z >= 0 && v.z < OPT) atomicAdd(&h[v.z], 1);
        if (v.w >= 0 && v.w < OPT) atomicAdd(&h[v.w], 1);
    } else {
        for (int i = i4 * 4; i < min(i4 * 4 + 4, B); i++) {
            int e = idx[i];
            if (e >= 0 && e < OPT) atomicAdd(&h[e], 1);
        }
    }
    __syncthreads();
    if (t < OPT) g_blockhist[blockIdx.x][t] = h[t];
}

__global__ void scan_kernel(int B) {
    __shared__ int tot[OPT];
    __shared__ int off[OPT];
    __shared__ int toff[OPT];
    int e = threadIdx.x;  // 64 threads
    int nblk = (B + 1023) / 1024;
    int s = 0;
    for (int b = 0; b < nblk; b++) s += g_blockhist[b][e];
    tot[e] = s;
    __syncthreads();
    if (e == 0) {
        int acc = 0, tacc = 0;
        for (int i = 0; i < OPT; i++) {
            off[i] = acc; acc += tot[i];
            toff[i] = tacc; tacc += (tot[i] + TILE_M - 1) / TILE_M;
        }
        g_ntiles = tacc;
    }
    __syncthreads();
    int run = off[e];
    for (int b = 0; b < nblk; b++) { g_blockbase[b][e] = run; run += g_blockhist[b][e]; }
    g_expert_end[e] = off[e] + tot[e];
    int nt = (tot[e] + TILE_M - 1) / TILE_M;
    for (int i = 0; i < nt; i++) {
        g_tile_e[toff[e] + i] = e;
        g_tile_m0[toff[e] + i] = off[e] + i * TILE_M;
    }
}

__global__ void scatter_kernel(const int* __restrict__ idx, int B) {
    __shared__ int cur[OPT];
    int t = threadIdx.x;
    if (t < OPT) cur[t] = 0;
    __syncthreads();
    int i4 = blockIdx.x * 256 + t;
    if (i4 * 4 + 3 < B) {
        int4 v = ((const int4*)idx)[i4];
        int es[4] = {v.x, v.y, v.z, v.w};
        #pragma unroll
        for (int j = 0; j < 4; j++) {
            int e = es[j];
            if (e >= 0 && e < OPT) {
                int r = atomicAdd(&cur[e], 1);
                g_rowids[g_blockbase[blockIdx.x][e] + r] = i4 * 4 + j;
            }
        }
    } else {
        for (int i = i4 * 4; i < min(i4 * 4 + 4, B); i++) {
            int e = idx[i];
            if (e >= 0 && e < OPT) {
                int r = atomicAdd(&cur[e], 1);
                g_rowids[g_blockbase[blockIdx.x][e] + r] = i;
            }
        }
    }
}

// ---------------- Compute: warp-level bf16 mma.sync (sm_80 PTX, works on sm_103) ----
// Tile 128(M) x 128(N) x 128(K). 8 warps: warp_m = wid&3 (32 rows), warp_n = wid>>2 (64 cols).
// bf16 3-term split: hiA*hiB + hiA*loB + loA*hiB; fp32 accum. Dropped lo*lo ~2^-16 rel.

#define LDA 136          // padded row stride (elements); 272B = 17*16B -> ldmatrix conflict-free
#define SA_HI 0
#define SA_LO (TILE_M * LDA * 2)              // 34816
#define SB_HI (2 * TILE_M * LDA * 2)          // 69632
#define SB_LO (3 * TILE_M * LDA * 2)          // 104448
#define SROW  (4 * TILE_M * LDA * 2)          // 139264
#define SBIAS (SROW + 512)
#define SMEM_BYTES (SBIAS + 512)              // 140288
#define NT 256

__device__ __forceinline__ uint32_t smem_u32(const void* p) {
    uint32_t a;
    asm("{ .reg .u64 tmp; cvta.to.shared.u64 tmp, %1; cvt.u32.u64 %0, tmp; }"
        : "=r"(a) : "l"(p));
    return a;
}

__device__ __forceinline__ void ldsm_x4(uint32_t* r, uint32_t addr) {
    asm volatile("ldmatrix.sync.aligned.m8n8.x4.shared.b16 {%0,%1,%2,%3}, [%4];"
        : "=r"(r[0]), "=r"(r[1]), "=r"(r[2]), "=r"(r[3]) : "r"(addr));
}

__device__ __forceinline__ void ldsm_x4t(uint32_t* r, uint32_t addr) {
    asm volatile("ldmatrix.sync.aligned.m8n8.x4.trans.shared.b16 {%0,%1,%2,%3}, [%4];"
        : "=r"(r[0]), "=r"(r[1]), "=r"(r[2]), "=r"(r[3]) : "r"(addr));
}

__device__ __forceinline__ void mma_bf16(float* c, const uint32_t* a, const uint32_t* b) {
    asm volatile(
        "mma.sync.aligned.m16n8k16.row.col.f32.bf16.bf16.f32 "
        "{%0,%1,%2,%3}, {%4,%5,%6,%7}, {%8,%9}, {%0,%1,%2,%3};"
        : "+f"(c[0]), "+f"(c[1]), "+f"(c[2]), "+f"(c[3])
        : "r"(a[0]), "r"(a[1]), "r"(a[2]), "r"(a[3]), "r"(b[0]), "r"(b[1]));
}

__device__ __forceinline__ uint32_t pack_bf2(__nv_bfloat16 lo, __nv_bfloat16 hi) {
    return ((uint32_t)__bfloat16_as_ushort(hi) << 16) | __bfloat16_as_ushort(lo);
}

// split 8 consecutive floats into packed bf16 hi/lo uint4's
__device__ __forceinline__ void split8(const float* vv, uint4& ph4, uint4& pl4) {
    uint32_t ph[4], pl[4];
    #pragma unroll
    for (int j = 0; j < 4; j++) {
        __nv_bfloat16 h0 = __float2bfloat16_rn(vv[2 * j]);
        __nv_bfloat16 h1 = __float2bfloat16_rn(vv[2 * j + 1]);
        __nv_bfloat16 l0 = __float2bfloat16_rn(vv[2 * j] - __bfloat162float(h0));
        __nv_bfloat16 l1 = __float2bfloat16_rn(vv[2 * j + 1] - __bfloat162float(h1));
        ph[j] = pack_bf2(h0, h1);
        pl[j] = pack_bf2(l0, l1);
    }
    ph4 = make_uint4(ph[0], ph[1], ph[2], ph[3]);
    pl4 = make_uint4(pl[0], pl[1], pl[2], pl[3]);
}

__global__ __launch_bounds__(NT, 1)
void mm_kernel(const float* __restrict__ x, const float* __restrict__ w,
               const float* __restrict__ bias, float* __restrict__ out) {
    int tile = blockIdx.x;
    if (tile >= g_ntiles) return;
    int e = g_tile_e[tile];
    int m0 = g_tile_m0[tile];
    int mcnt = min(TILE_M, g_expert_end[e] - m0);

    extern __shared__ char smem[];
    uint32_t sb = smem_u32(smem);
    int t = threadIdx.x;
    int wid = t >> 5;
    int lane = t & 31;

    int* srow = (int*)(smem + SROW);
    float* sbias = (float*)(smem + SBIAS);

    if (t < TILE_M) srow[t] = g_rowids[m0 + min(t, mcnt - 1)];
    if (t < DOUT) sbias[t] = bias[(size_t)e * DOUT + t];
    __syncthreads();   // srow needed by A staging below

    // ---- Stage A: gathered x rows -> bf16 hi/lo [128][136] ----
    for (int i = t; i < TILE_M * (DIN / 8); i += NT) {
        int m = i >> 4;
        int k0 = (i & 15) * 8;
        int gr = srow[m];
        float4 v0 = *(const float4*)(x + (size_t)gr * DIN + k0);
        float4 v1 = *(const float4*)(x + (size_t)gr * DIN + k0 + 4);
        float vv[8] = {v0.x, v0.y, v0.z, v0.w, v1.x, v1.y, v1.z, v1.w};
        uint4 ph4, pl4;
        split8(vv, ph4, pl4);
        uint32_t off = (uint32_t)(m * LDA + k0) * 2;
        *(uint4*)(smem + SA_HI + off) = ph4;
        *(uint4*)(smem + SA_LO + off) = pl4;
    }

    // ---- Stage B: w[e] natural [k][o] -> bf16 hi/lo [128][136] ----
    for (int i = t; i < DIN * (DOUT / 8); i += NT) {
        int k = i >> 4;
        int o0 = (i & 15) * 8;
        const float* wr = w + (size_t)e * DIN * DOUT + (size_t)k * DOUT + o0;
        float4 v0 = *(const float4*)(wr);
        float4 v1 = *(const float4*)(wr + 4);
        float vv[8] = {v0.x, v0.y, v0.z, v0.w, v1.x, v1.y, v1.z, v1.w};
        uint4 ph4, pl4;
        split8(vv, ph4, pl4);
        uint32_t off = (uint32_t)(k * LDA + o0) * 2;
        *(uint4*)(smem + SB_HI + off) = ph4;
        *(uint4*)(smem + SB_LO + off) = pl4;
    }
    __syncthreads();

    // ---- MMA mainloop ----
    int warp_m = wid & 3;     // 32-row slab
    int warp_n = wid >> 2;    // 64-col slab

    float acc[2][8][4];
    #pragma unroll
    for (int mt = 0; mt < 2; mt++)
        #pragma unroll
        for (int nt = 0; nt < 8; nt++)
            #pragma unroll
            for (int j = 0; j < 4; j++) acc[mt][nt][j] = 0.0f;

    // A ldmatrix address: row = mbase + (lane&15), col = k0 + 8*(lane>>4)
    int a_r = warp_m * 32 + (lane & 15);
    int a_c8 = (lane >> 4) << 3;
    // B ldmatrix (trans): row = k0 + (lane&7) + 8*((lane>>3)&1), col = n0 + 8*(lane>>4)
    int b_rk = (lane & 7) + (((lane >> 3) & 1) << 3);
    int b_c8 = (lane >> 4) << 3;

    #pragma unroll
    for (int ks = 0; ks < 8; ks++) {
        int k0 = ks * 16;
        uint32_t Ah[2][4], Al[2][4];
        #pragma unroll
        for (int mt = 0; mt < 2; mt++) {
            uint32_t off = (uint32_t)((a_r + mt * 16) * LDA + k0 + a_c8) * 2;
            ldsm_x4(Ah[mt], sb + SA_HI + off);
            ldsm_x4(Al[mt], sb + SA_LO + off);
        }
        #pragma unroll
        for (int np = 0; np < 4; np++) {
            int n0 = warp_n * 64 + np * 16;
            uint32_t boff = (uint32_t)((k0 + b_rk) * LDA + n0 + b_c8) * 2;
            uint32_t Bh[4], Bl[4];
            ldsm_x4t(Bh, sb + SB_HI + boff);
            ldsm_x4t(Bl, sb + SB_LO + boff);
            #pragma unroll
            for (int mt = 0; mt < 2; mt++) {
                mma_bf16(acc[mt][2 * np + 0], Ah[mt], Bh + 0);
                mma_bf16(acc[mt][2 * np + 1], Ah[mt], Bh + 2);
                mma_bf16(acc[mt][2 * np + 0], Ah[mt], Bl + 0);
                mma_bf16(acc[mt][2 * np + 1], Ah[mt], Bl + 2);
                mma_bf16(acc[mt][2 * np + 0], Al[mt], Bh + 0);
                mma_bf16(acc[mt][2 * np + 1], Al[mt], Bh + 2);
            }
        }
    }

    // ---- Epilogue: bias + scatter back to out rows ----
    int g4 = lane >> 2;
    int t4 = lane & 3;
    #pragma unroll
    for (int mt = 0; mt < 2; mt++) {
        #pragma unroll
        for (int half = 0; half < 2; half++) {
            int m = warp_m * 32 + mt * 16 + half * 8 + g4;
            if (m < mcnt) {
                int gr = srow[m];
                float* orow = out + (size_t)gr * DOUT;
                #pragma unroll
                for (int nt = 0; nt < 8; nt++) {
                    int c = warp_n * 64 + nt * 8 + t4 * 2;
                    float2 v;
                    v.x = acc[mt][nt][half * 2 + 0] + sbias[c];
                    v.y = acc[mt][nt][half * 2 + 1] + sbias[c + 1];
                    *(float2*)(orow + c) = v;
                }
            }
        }
    }
}

extern "C" void kernel_launch(void* const* d_in, const int* in_sizes, int n_in,
                              void* d_out, int out_size) {
    const float* x = (const float*)d_in[0];
    const float* w = (const float*)d_in[1];
    const float* b = (const float*)d_in[2];
    const int* idx = (const int*)d_in[3];   // JAX x64-disabled: indices arrive int32
    float* out = (float*)d_out;
    int B = in_sizes[3];
    if (B > MAX_B) B = MAX_B;

    cudaFuncSetAttribute(mm_kernel, cudaFuncAttributeMaxDynamicSharedMemorySize,
                         SMEM_BYTES);

    int nblk = (B + 1023) / 1024;
    hist_kernel<<<nblk, 256>>>(idx, B);
    scan_kernel<<<1, 64>>>(B);
    scatter_kernel<<<nblk, 256>>>(idx, B);
    mm_kernel<<<MAX_TILES, NT, SMEM_BYTES>>>(x, w, b, out);
}

// round 9
// speedup vs baseline: 1.1211x; 1.1211x over previous
#include <cuda_runtime.h>
#include <cuda_bf16.h>
#include <cstdint>

#define OPT 64
#define DIN 128
#define DOUT 128
#define TILE_M 128
#define MAX_B 16384
#define HBLK 16
#define MAX_TILES (MAX_B / TILE_M + OPT)      // 192

// ---- scratch (device allocation banned) ----
__device__ int g_blockhist[HBLK][OPT];
__device__ int g_blockbase[HBLK][OPT];
__device__ int g_expert_end[OPT];
__device__ int g_rowids[MAX_B];
__device__ int g_ntiles;
__device__ int g_tile_e[MAX_TILES];
__device__ int g_tile_m0[MAX_TILES];

// ---------------- Prelude: counting sort by expert (smem atomics only) ----------------

__global__ void hist_kernel(const int* __restrict__ idx, int B) {
    __shared__ int h[OPT];
    int t = threadIdx.x;
    if (t < OPT) h[t] = 0;
    __syncthreads();
    int i4 = blockIdx.x * 256 + t;
    if (i4 * 4 + 3 < B) {
        int4 v = ((const int4*)idx)[i4];
        if (v.x >= 0 && v.x < OPT) atomicAdd(&h[v.x], 1);
        if (v.y >= 0 && v.y < OPT) atomicAdd(&h[v.y], 1);
        if (v.z >= 0 && v.z < OPT) atomicAdd(&h[v.z], 1);
        if (v.w >= 0 && v.w < OPT) atomicAdd(&h[v.w], 1);
    } else {
        for (int i = i4 * 4; i < min(i4 * 4 + 4, B); i++) {
            int e = idx[i];
            if (e >= 0 && e < OPT) atomicAdd(&h[e], 1);
        }
    }
    __syncthreads();
    if (t < OPT) g_blockhist[blockIdx.x][t] = h[t];
}

__global__ void scan_kernel(int B) {
    __shared__ int tot[OPT];
    __shared__ int off[OPT];
    __shared__ int toff[OPT];
    int e = threadIdx.x;  // 64 threads
    int nblk = (B + 1023) / 1024;
    int s = 0;
    for (int b = 0; b < nblk; b++) s += g_blockhist[b][e];
    tot[e] = s;
    __syncthreads();
    if (e == 0) {
        int acc = 0, tacc = 0;
        for (int i = 0; i < OPT; i++) {
            off[i] = acc; acc += tot[i];
            toff[i] = tacc; tacc += (tot[i] + TILE_M - 1) / TILE_M;
        }
        g_ntiles = tacc;
    }
    __syncthreads();
    int run = off[e];
    for (int b = 0; b < nblk; b++) { g_blockbase[b][e] = run; run += g_blockhist[b][e]; }
    g_expert_end[e] = off[e] + tot[e];
    int nt = (tot[e] + TILE_M - 1) / TILE_M;
    for (int i = 0; i < nt; i++) {
        g_tile_e[toff[e] + i] = e;
        g_tile_m0[toff[e] + i] = off[e] + i * TILE_M;
    }
}

__global__ void scatter_kernel(const int* __restrict__ idx, int B) {
    __shared__ int cur[OPT];
    int t = threadIdx.x;
    if (t < OPT) cur[t] = 0;
    __syncthreads();
    int i4 = blockIdx.x * 256 + t;
    if (i4 * 4 + 3 < B) {
        int4 v = ((const int4*)idx)[i4];
        int es[4] = {v.x, v.y, v.z, v.w};
        #pragma unroll
        for (int j = 0; j < 4; j++) {
            int e = es[j];
            if (e >= 0 && e < OPT) {
                int r = atomicAdd(&cur[e], 1);
                g_rowids[g_blockbase[blockIdx.x][e] + r] = i4 * 4 + j;
            }
        }
    } else {
        for (int i = i4 * 4; i < min(i4 * 4 + 4, B); i++) {
            int e = idx[i];
            if (e >= 0 && e < OPT) {
                int r = atomicAdd(&cur[e], 1);
                g_rowids[g_blockbase[blockIdx.x][e] + r] = i;
            }
        }
    }
}

// ---------------- Compute: warp-level bf16 mma.sync, 512 threads ----------------
// Tile 128(M) x 128(N) x 128(K). 16 warps in 4x4 grid: warp_m = wid&3 (32 rows),
// warp_n = wid>>2 (32 cols). bf16 3-term split, fp32 accum.

#define LDA 136          // padded row stride (elements); conflict-free ldmatrix
#define SA_HI 0
#define SA_LO (TILE_M * LDA * 2)              // 34816
#define SB_HI (2 * TILE_M * LDA * 2)          // 69632
#define SB_LO (3 * TILE_M * LDA * 2)          // 104448
#define SROW  (4 * TILE_M * LDA * 2)          // 139264
#define SBIAS (SROW + 512)
#define SMEM_BYTES (SBIAS + 512)              // 140288
#define NT 512

__device__ __forceinline__ uint32_t smem_u32(const void* p) {
    uint32_t a;
    asm("{ .reg .u64 tmp; cvta.to.shared.u64 tmp, %1; cvt.u32.u64 %0, tmp; }"
        : "=r"(a) : "l"(p));
    return a;
}

__device__ __forceinline__ void ldsm_x4(uint32_t* r, uint32_t addr) {
    asm volatile("ldmatrix.sync.aligned.m8n8.x4.shared.b16 {%0,%1,%2,%3}, [%4];"
        : "=r"(r[0]), "=r"(r[1]), "=r"(r[2]), "=r"(r[3]) : "r"(addr));
}

__device__ __forceinline__ void ldsm_x4t(uint32_t* r, uint32_t addr) {
    asm volatile("ldmatrix.sync.aligned.m8n8.x4.trans.shared.b16 {%0,%1,%2,%3}, [%4];"
        : "=r"(r[0]), "=r"(r[1]), "=r"(r[2]), "=r"(r[3]) : "r"(addr));
}

__device__ __forceinline__ void mma_bf16(float* c, const uint32_t* a, const uint32_t* b) {
    asm volatile(
        "mma.sync.aligned.m16n8k16.row.col.f32.bf16.bf16.f32 "
        "{%0,%1,%2,%3}, {%4,%5,%6,%7}, {%8,%9}, {%0,%1,%2,%3};"
        : "+f"(c[0]), "+f"(c[1]), "+f"(c[2]), "+f"(c[3])
        : "r"(a[0]), "r"(a[1]), "r"(a[2]), "r"(a[3]), "r"(b[0]), "r"(b[1]));
}

__device__ __forceinline__ uint32_t pack_bf2(__nv_bfloat16 lo, __nv_bfloat16 hi) {
    return ((uint32_t)__bfloat16_as_ushort(hi) << 16) | __bfloat16_as_ushort(lo);
}

__device__ __forceinline__ void split8(const float* vv, uint4& ph4, uint4& pl4) {
    uint32_t ph[4], pl[4];
    #pragma unroll
    for (int j = 0; j < 4; j++) {
        __nv_bfloat16 h0 = __float2bfloat16_rn(vv[2 * j]);
        __nv_bfloat16 h1 = __float2bfloat16_rn(vv[2 * j + 1]);
        __nv_bfloat16 l0 = __float2bfloat16_rn(vv[2 * j] - __bfloat162float(h0));
        __nv_bfloat16 l1 = __float2bfloat16_rn(vv[2 * j + 1] - __bfloat162float(h1));
        ph[j] = pack_bf2(h0, h1);
        pl[j] = pack_bf2(l0, l1);
    }
    ph4 = make_uint4(ph[0], ph[1], ph[2], ph[3]);
    pl4 = make_uint4(pl[0], pl[1], pl[2], pl[3]);
}

__global__ __launch_bounds__(NT, 1)
void mm_kernel(const float* __restrict__ x, const float* __restrict__ w,
               const float* __restrict__ bias, float* __restrict__ out) {
    int tile = blockIdx.x;
    if (tile >= g_ntiles) return;
    int e = g_tile_e[tile];
    int m0 = g_tile_m0[tile];
    int mcnt = min(TILE_M, g_expert_end[e] - m0);

    extern __shared__ char smem[];
    uint32_t sb = smem_u32(smem);
    int t = threadIdx.x;
    int wid = t >> 5;
    int lane = t & 31;

    int* srow = (int*)(smem + SROW);
    float* sbias = (float*)(smem + SBIAS);

    if (t < TILE_M) srow[t] = g_rowids[m0 + min(t, mcnt - 1)];
    if (t >= 128 && t < 128 + DOUT) sbias[t - 128] = bias[(size_t)e * DOUT + t - 128];
    __syncthreads();   // srow needed by A staging below

    // ---- Stage A: gathered x rows -> bf16 hi/lo [128][136] (4 iters/thread) ----
    for (int i = t; i < TILE_M * (DIN / 8); i += NT) {
        int m = i >> 4;
        int k0 = (i & 15) * 8;
        int gr = srow[m];
        float4 v0 = *(const float4*)(x + (size_t)gr * DIN + k0);
        float4 v1 = *(const float4*)(x + (size_t)gr * DIN + k0 + 4);
        float vv[8] = {v0.x, v0.y, v0.z, v0.w, v1.x, v1.y, v1.z, v1.w};
        uint4 ph4, pl4;
        split8(vv, ph4, pl4);
        uint32_t off = (uint32_t)(m * LDA + k0) * 2;
        *(uint4*)(smem + SA_HI + off) = ph4;
        *(uint4*)(smem + SA_LO + off) = pl4;
    }

    // ---- Stage B: w[e] natural [k][o] -> bf16 hi/lo [128][136] (4 iters/thread) ----
    for (int i = t; i < DIN * (DOUT / 8); i += NT) {
        int k = i >> 4;
        int o0 = (i & 15) * 8;
        const float* wr = w + (size_t)e * DIN * DOUT + (size_t)k * DOUT + o0;
        float4 v0 = *(const float4*)(wr);
        float4 v1 = *(const float4*)(wr + 4);
        float vv[8] = {v0.x, v0.y, v0.z, v0.w, v1.x, v1.y, v1.z, v1.w};
        uint4 ph4, pl4;
        split8(vv, ph4, pl4);
        uint32_t off = (uint32_t)(k * LDA + o0) * 2;
        *(uint4*)(smem + SB_HI + off) = ph4;
        *(uint4*)(smem + SB_LO + off) = pl4;
    }
    __syncthreads();

    // ---- MMA mainloop: warp = (warp_m, warp_n), M32 x N32 ----
    int warp_m = wid & 3;
    int warp_n = wid >> 2;

    float acc[2][4][4];     // [mt][n8-tile][frag]
    #pragma unroll
    for (int mt = 0; mt < 2; mt++)
        #pragma unroll
        for (int nt = 0; nt < 4; nt++)
            #pragma unroll
            for (int j = 0; j < 4; j++) acc[mt][nt][j] = 0.0f;

    int a_r = warp_m * 32 + (lane & 15);
    int a_c8 = (lane >> 4) << 3;
    int b_rk = (lane & 7) + (((lane >> 3) & 1) << 3);
    int b_c8 = (lane >> 4) << 3;

    #pragma unroll
    for (int ks = 0; ks < 8; ks++) {
        int k0 = ks * 16;
        uint32_t Ah[2][4], Al[2][4];
        #pragma unroll
        for (int mt = 0; mt < 2; mt++) {
            uint32_t off = (uint32_t)((a_r + mt * 16) * LDA + k0 + a_c8) * 2;
            ldsm_x4(Ah[mt], sb + SA_HI + off);
            ldsm_x4(Al[mt], sb + SA_LO + off);
        }
        #pragma unroll
        for (int np = 0; np < 2; np++) {
            int n0 = warp_n * 32 + np * 16;
            uint32_t boff = (uint32_t)((k0 + b_rk) * LDA + n0 + b_c8) * 2;
            uint32_t Bh[4], Bl[4];
            ldsm_x4t(Bh, sb + SB_HI + boff);
            ldsm_x4t(Bl, sb + SB_LO + boff);
            #pragma unroll
            for (int mt = 0; mt < 2; mt++) {
                mma_bf16(acc[mt][2 * np + 0], Ah[mt], Bh + 0);
                mma_bf16(acc[mt][2 * np + 1], Ah[mt], Bh + 2);
                mma_bf16(acc[mt][2 * np + 0], Ah[mt], Bl + 0);
                mma_bf16(acc[mt][2 * np + 1], Ah[mt], Bl + 2);
                mma_bf16(acc[mt][2 * np + 0], Al[mt], Bh + 0);
                mma_bf16(acc[mt][2 * np + 1], Al[mt], Bh + 2);
            }
        }
    }

    // ---- Epilogue: bias + scatter to out rows ----
    int g4 = lane >> 2;
    int t4 = lane & 3;
    #pragma unroll
    for (int mt = 0; mt < 2; mt++) {
        #pragma unroll
        for (int half = 0; half < 2; half++) {
            int m = warp_m * 32 + mt * 16 + half * 8 + g4;
            if (m < mcnt) {
                int gr = srow[m];
                float* orow = out + (size_t)gr * DOUT;
                #pragma unroll
                for (int nt = 0; nt < 4; nt++) {
                    int c = warp_n * 32 + nt * 8 + t4 * 2;
                    float2 v;
                    v.x = acc[mt][nt][half * 2 + 0] + sbias[c];
                    v.y = acc[mt][nt][half * 2 + 1] + sbias[c + 1];
                    *(float2*)(orow + c) = v;
                }
            }
        }
    }
}

extern "C" void kernel_launch(void* const* d_in, const int* in_sizes, int n_in,
                              void* d_out, int out_size) {
    const float* x = (const float*)d_in[0];
    const float* w = (const float*)d_in[1];
    const float* b = (const float*)d_in[2];
    const int* idx = (const int*)d_in[3];   // JAX x64-disabled: indices arrive int32
    float* out = (float*)d_out;
    int B = in_sizes[3];
    if (B > MAX_B) B = MAX_B;

    cudaFuncSetAttribute(mm_kernel, cudaFuncAttributeMaxDynamicSharedMemorySize,
                         SMEM_BYTES);

    int nblk = (B + 1023) / 1024;
    hist_kernel<<<nblk, 256>>>(idx, B);
    scan_kernel<<<1, 64>>>(B);
    scatter_kernel<<<nblk, 256>>>(idx, B);
    mm_kernel<<<MAX_TILES, NT, SMEM_BYTES>>>(x, w, b, out);
}

// round 10
// speedup vs baseline: 1.1889x; 1.0605x over previous
#include <cuda_runtime.h>
#include <cuda_bf16.h>
#include <cstdint>

#define OPT 64
#define DIN 128
#define DOUT 128
#define TILE_M 64
#define MAX_B 16384
#define HBLK 16
#define MAX_TILES (MAX_B / TILE_M + OPT)      // 320

// ---- scratch (device allocation banned) ----
__device__ int g_blockhist[HBLK][OPT];
__device__ int g_blockbase[HBLK][OPT];
__device__ int g_expert_end[OPT];
__device__ int g_rowids[MAX_B];
__device__ int g_ntiles;
__device__ int g_tile_e[MAX_TILES];
__device__ int g_tile_m0[MAX_TILES];

// ---------------- Prelude: counting sort by expert (smem atomics only) ----------------

__global__ void hist_kernel(const int* __restrict__ idx, int B) {
    __shared__ int h[OPT];
    int t = threadIdx.x;
    if (t < OPT) h[t] = 0;
    __syncthreads();
    int i4 = blockIdx.x * 256 + t;
    if (i4 * 4 + 3 < B) {
        int4 v = ((const int4*)idx)[i4];
        if (v.x >= 0 && v.x < OPT) atomicAdd(&h[v.x], 1);
        if (v.y >= 0 && v.y < OPT) atomicAdd(&h[v.y], 1);
        if (v.z >= 0 && v.z < OPT) atomicAdd(&h[v.z], 1);
        if (v.w >= 0 && v.w < OPT) atomicAdd(&h[v.w], 1);
    } else {
        for (int i = i4 * 4; i < min(i4 * 4 + 4, B); i++) {
            int e = idx[i];
            if (e >= 0 && e < OPT) atomicAdd(&h[e], 1);
        }
    }
    __syncthreads();
    if (t < OPT) g_blockhist[blockIdx.x][t] = h[t];
}

__global__ void scan_kernel(int B) {
    __shared__ int tot[OPT];
    __shared__ int off[OPT];
    __shared__ int toff[OPT];
    int e = threadIdx.x;  // 64 threads
    int nblk = (B + 1023) / 1024;
    int s = 0;
    for (int b = 0; b < nblk; b++) s += g_blockhist[b][e];
    tot[e] = s;
    __syncthreads();
    if (e == 0) {
        int acc = 0, tacc = 0;
        for (int i = 0; i < OPT; i++) {
            off[i] = acc; acc += tot[i];
            toff[i] = tacc; tacc += (tot[i] + TILE_M - 1) / TILE_M;
        }
        g_ntiles = tacc;
    }
    __syncthreads();
    int run = off[e];
    for (int b = 0; b < nblk; b++) { g_blockbase[b][e] = run; run += g_blockhist[b][e]; }
    g_expert_end[e] = off[e] + tot[e];
    int nt = (tot[e] + TILE_M - 1) / TILE_M;
    for (int i = 0; i < nt; i++) {
        g_tile_e[toff[e] + i] = e;
        g_tile_m0[toff[e] + i] = off[e] + i * TILE_M;
    }
}

__global__ void scatter_kernel(const int* __restrict__ idx, int B) {
    __shared__ int cur[OPT];
    int t = threadIdx.x;
    if (t < OPT) cur[t] = 0;
    __syncthreads();
    int i4 = blockIdx.x * 256 + t;
    if (i4 * 4 + 3 < B) {
        int4 v = ((const int4*)idx)[i4];
        int es[4] = {v.x, v.y, v.z, v.w};
        #pragma unroll
        for (int j = 0; j < 4; j++) {
            int e = es[j];
            if (e >= 0 && e < OPT) {
                int r = atomicAdd(&cur[e], 1);
                g_rowids[g_blockbase[blockIdx.x][e] + r] = i4 * 4 + j;
            }
        }
    } else {
        for (int i = i4 * 4; i < min(i4 * 4 + 4, B); i++) {
            int e = idx[i];
            if (e >= 0 && e < OPT) {
                int r = atomicAdd(&cur[e], 1);
                g_rowids[g_blockbase[blockIdx.x][e] + r] = i;
            }
        }
    }
}

// ---------------- Compute: warp-level bf16 mma.sync ----------------
// Tile 64(M) x 128(N) x 128(K). 8 warps in 2x4 grid: warp_m = wid&1 (32 rows),
// warp_n = wid>>1 (32 cols). bf16 3-term split, fp32 accum. 2 blocks/SM.

#define LDA 136          // padded row stride (elements); conflict-free ldmatrix
#define SA_HI 0
#define SA_LO (TILE_M * LDA * 2)                      // 17408
#define SB_HI (2 * TILE_M * LDA * 2)                  // 34816
#define SB_LO (2 * TILE_M * LDA * 2 + DIN * LDA * 2)  // 69632
#define SROW  (2 * TILE_M * LDA * 2 + 2 * DIN * LDA * 2)  // 104448
#define SBIAS (SROW + 256)
#define SMEM_BYTES (SBIAS + 512)                      // 105216
#define NT 256

__device__ __forceinline__ uint32_t smem_u32(const void* p) {
    uint32_t a;
    asm("{ .reg .u64 tmp; cvta.to.shared.u64 tmp, %1; cvt.u32.u64 %0, tmp; }"
        : "=r"(a) : "l"(p));
    return a;
}

__device__ __forceinline__ void ldsm_x4(uint32_t* r, uint32_t addr) {
    asm volatile("ldmatrix.sync.aligned.m8n8.x4.shared.b16 {%0,%1,%2,%3}, [%4];"
        : "=r"(r[0]), "=r"(r[1]), "=r"(r[2]), "=r"(r[3]) : "r"(addr));
}

__device__ __forceinline__ void ldsm_x4t(uint32_t* r, uint32_t addr) {
    asm volatile("ldmatrix.sync.aligned.m8n8.x4.trans.shared.b16 {%0,%1,%2,%3}, [%4];"
        : "=r"(r[0]), "=r"(r[1]), "=r"(r[2]), "=r"(r[3]) : "r"(addr));
}

__device__ __forceinline__ void mma_bf16(float* c, const uint32_t* a, const uint32_t* b) {
    asm volatile(
        "mma.sync.aligned.m16n8k16.row.col.f32.bf16.bf16.f32 "
        "{%0,%1,%2,%3}, {%4,%5,%6,%7}, {%8,%9}, {%0,%1,%2,%3};"
        : "+f"(c[0]), "+f"(c[1]), "+f"(c[2]), "+f"(c[3])
        : "r"(a[0]), "r"(a[1]), "r"(a[2]), "r"(a[3]), "r"(b[0]), "r"(b[1]));
}

__device__ __forceinline__ uint32_t pack_bf2(__nv_bfloat16 lo, __nv_bfloat16 hi) {
    return ((uint32_t)__bfloat16_as_ushort(hi) << 16) | __bfloat16_as_ushort(lo);
}

__device__ __forceinline__ void split8(const float* vv, uint4& ph4, uint4& pl4) {
    uint32_t ph[4], pl[4];
    #pragma unroll
    for (int j = 0; j < 4; j++) {
        __nv_bfloat16 h0 = __float2bfloat16_rn(vv[2 * j]);
        __nv_bfloat16 h1 = __float2bfloat16_rn(vv[2 * j + 1]);
        __nv_bfloat16 l0 = __float2bfloat16_rn(vv[2 * j] - __bfloat162float(h0));
        __nv_bfloat16 l1 = __float2bfloat16_rn(vv[2 * j + 1] - __bfloat162float(h1));
        ph[j] = pack_bf2(h0, h1);
        pl[j] = pack_bf2(l0, l1);
    }
    ph4 = make_uint4(ph[0], ph[1], ph[2], ph[3]);
    pl4 = make_uint4(pl[0], pl[1], pl[2], pl[3]);
}

__global__ __launch_bounds__(NT, 2)
void mm_kernel(const float* __restrict__ x, const float* __restrict__ w,
               const float* __restrict__ bias, float* __restrict__ out) {
    int tile = blockIdx.x;
    if (tile >= g_ntiles) return;
    int e = g_tile_e[tile];
    int m0 = g_tile_m0[tile];
    int mcnt = min(TILE_M, g_expert_end[e] - m0);

    extern __shared__ char smem[];
    uint32_t sb = smem_u32(smem);
    int t = threadIdx.x;
    int wid = t >> 5;
    int lane = t & 31;

    int* srow = (int*)(smem + SROW);
    float* sbias = (float*)(smem + SBIAS);

    if (t < TILE_M) srow[t] = g_rowids[m0 + min(t, mcnt - 1)];
    if (t >= 64 && t < 64 + DOUT) sbias[t - 64] = bias[(size_t)e * DOUT + t - 64];
    __syncthreads();   // srow needed by A staging below

    // ---- Stage A: gathered x rows -> bf16 hi/lo [64][136] (4 iters/thread) ----
    for (int i = t; i < TILE_M * (DIN / 8); i += NT) {
        int m = i >> 4;
        int k0 = (i & 15) * 8;
        int gr = srow[m];
        float4 v0 = *(const float4*)(x + (size_t)gr * DIN + k0);
        float4 v1 = *(const float4*)(x + (size_t)gr * DIN + k0 + 4);
        float vv[8] = {v0.x, v0.y, v0.z, v0.w, v1.x, v1.y, v1.z, v1.w};
        uint4 ph4, pl4;
        split8(vv, ph4, pl4);
        uint32_t off = (uint32_t)(m * LDA + k0) * 2;
        *(uint4*)(smem + SA_HI + off) = ph4;
        *(uint4*)(smem + SA_LO + off) = pl4;
    }

    // ---- Stage B: w[e] natural [k][o] -> bf16 hi/lo [128][136] (8 iters/thread) ----
    for (int i = t; i < DIN * (DOUT / 8); i += NT) {
        int k = i >> 4;
        int o0 = (i & 15) * 8;
        const float* wr = w + (size_t)e * DIN * DOUT + (size_t)k * DOUT + o0;
        float4 v0 = *(const float4*)(wr);
        float4 v1 = *(const float4*)(wr + 4);
        float vv[8] = {v0.x, v0.y, v0.z, v0.w, v1.x, v1.y, v1.z, v1.w};
        uint4 ph4, pl4;
        split8(vv, ph4, pl4);
        uint32_t off = (uint32_t)(k * LDA + o0) * 2;
        *(uint4*)(smem + SB_HI + off) = ph4;
        *(uint4*)(smem + SB_LO + off) = pl4;
    }
    __syncthreads();

    // ---- MMA mainloop: warp = (warp_m, warp_n), M32 x N32 ----
    int warp_m = wid & 1;
    int warp_n = wid >> 1;

    float acc[2][4][4];     // [mt][n8-tile][frag]
    #pragma unroll
    for (int mt = 0; mt < 2; mt++)
        #pragma unroll
        for (int nt = 0; nt < 4; nt++)
            #pragma unroll
            for (int j = 0; j < 4; j++) acc[mt][nt][j] = 0.0f;

    int a_r = warp_m * 32 + (lane & 15);
    int a_c8 = (lane >> 4) << 3;
    int b_rk = (lane & 7) + (((lane >> 3) & 1) << 3);
    int b_c8 = (lane >> 4) << 3;

    #pragma unroll
    for (int ks = 0; ks < 8; ks++) {
        int k0 = ks * 16;
        uint32_t Ah[2][4], Al[2][4];
        #pragma unroll
        for (int mt = 0; mt < 2; mt++) {
            uint32_t off = (uint32_t)((a_r + mt * 16) * LDA + k0 + a_c8) * 2;
            ldsm_x4(Ah[mt], sb + SA_HI + off);
            ldsm_x4(Al[mt], sb + SA_LO + off);
        }
        #pragma unroll
        for (int np = 0; np < 2; np++) {
            int n0 = warp_n * 32 + np * 16;
            uint32_t boff = (uint32_t)((k0 + b_rk) * LDA + n0 + b_c8) * 2;
            uint32_t Bh[4], Bl[4];
            ldsm_x4t(Bh, sb + SB_HI + boff);
            ldsm_x4t(Bl, sb + SB_LO + boff);
            #pragma unroll
            for (int mt = 0; mt < 2; mt++) {
                mma_bf16(acc[mt][2 * np + 0], Ah[mt], Bh + 0);
                mma_bf16(acc[mt][2 * np + 1], Ah[mt], Bh + 2);
                mma_bf16(acc[mt][2 * np + 0], Ah[mt], Bl + 0);
                mma_bf16(acc[mt][2 * np + 1], Ah[mt], Bl + 2);
                mma_bf16(acc[mt][2 * np + 0], Al[mt], Bh + 0);
                mma_bf16(acc[mt][2 * np + 1], Al[mt], Bh + 2);
            }
        }
    }

    // ---- Epilogue: bias + scatter to out rows ----
    int g4 = lane >> 2;
    int t4 = lane & 3;
    #pragma unroll
    for (int mt = 0; mt < 2; mt++) {
        #pragma unroll
        for (int half = 0; half < 2; half++) {
            int m = warp_m * 32 + mt * 16 + half * 8 + g4;
            if (m < mcnt) {
                int gr = srow[m];
                float* orow = out + (size_t)gr * DOUT;
                #pragma unroll
                for (int nt = 0; nt < 4; nt++) {
                    int c = warp_n * 32 + nt * 8 + t4 * 2;
                    float2 v;
                    v.x = acc[mt][nt][half * 2 + 0] + sbias[c];
                    v.y = acc[mt][nt][half * 2 + 1] + sbias[c + 1];
                    *(float2*)(orow + c) = v;
                }
            }
        }
    }
}

extern "C" void kernel_launch(void* const* d_in, const int* in_sizes, int n_in,
                              void* d_out, int out_size) {
    const float* x = (const float*)d_in[0];
    const float* w = (const float*)d_in[1];
    const float* b = (const float*)d_in[2];
    const int* idx = (const int*)d_in[3];   // JAX x64-disabled: indices arrive int32
    float* out = (float*)d_out;
    int B = in_sizes[3];
    if (B > MAX_B) B = MAX_B;

    cudaFuncSetAttribute(mm_kernel, cudaFuncAttributeMaxDynamicSharedMemorySize,
                         SMEM_BYTES);

    int nblk = (B + 1023) / 1024;
    hist_kernel<<<nblk, 256>>>(idx, B);
    scan_kernel<<<1, 64>>>(B);
    scatter_kernel<<<nblk, 256>>>(idx, B);
    mm_kernel<<<MAX_TILES, NT, SMEM_BYTES>>>(x, w, b, out);
}

// round 11
// speedup vs baseline: 1.3375x; 1.1250x over previous
#include <cuda_runtime.h>
#include <cuda_bf16.h>
#include <cstdint>

#define OPT 64
#define DIN 128
#define DOUT 128
#define TILE_M 64
#define MAX_B 16384
#define HBLK 16
#define MAX_TILES (MAX_B / TILE_M + OPT)      // 320

// ---- scratch (device allocation banned) ----
__device__ int g_blockhist[HBLK][OPT];
__device__ int g_blockbase[HBLK][OPT];
__device__ int g_expert_end[OPT];
__device__ int g_rowids[MAX_B];
__device__ int g_ntiles;
__device__ int g_tile_e[MAX_TILES];
__device__ int g_tile_m0[MAX_TILES];
// pre-split bf16 operands
__device__ __align__(16) __nv_bfloat16 g_xhi[MAX_B * DIN];
__device__ __align__(16) __nv_bfloat16 g_xlo[MAX_B * DIN];
__device__ __align__(16) __nv_bfloat16 g_whi[OPT * DIN * DOUT];
__device__ __align__(16) __nv_bfloat16 g_wlo[OPT * DIN * DOUT];

__device__ __forceinline__ uint32_t pack_bf2(__nv_bfloat16 lo, __nv_bfloat16 hi) {
    return ((uint32_t)__bfloat16_as_ushort(hi) << 16) | __bfloat16_as_ushort(lo);
}

__device__ __forceinline__ void split8(const float* vv, uint4& ph4, uint4& pl4) {
    uint32_t ph[4], pl[4];
    #pragma unroll
    for (int j = 0; j < 4; j++) {
        __nv_bfloat16 h0 = __float2bfloat16_rn(vv[2 * j]);
        __nv_bfloat16 h1 = __float2bfloat16_rn(vv[2 * j + 1]);
        __nv_bfloat16 l0 = __float2bfloat16_rn(vv[2 * j] - __bfloat162float(h0));
        __nv_bfloat16 l1 = __float2bfloat16_rn(vv[2 * j + 1] - __bfloat162float(h1));
        ph[j] = pack_bf2(h0, h1);
        pl[j] = pack_bf2(l0, l1);
    }
    ph4 = make_uint4(ph[0], ph[1], ph[2], ph[3]);
    pl4 = make_uint4(pl[0], pl[1], pl[2], pl[3]);
}

// ---------------- K1: hist (blocks 0..HBLK-1) + fp32->bf16 split (rest) ----------------

#define K1_BLOCKS 256

__global__ void hist_convert_kernel(const int* __restrict__ idx,
                                    const float* __restrict__ x,
                                    const float* __restrict__ w, int B) {
    int t = threadIdx.x;
    int b = blockIdx.x;
    if (b < HBLK) {
        __shared__ int h[OPT];
        if (t < OPT) h[t] = 0;
        __syncthreads();
        int i4 = b * 256 + t;
        if (i4 * 4 + 3 < B) {
            int4 v = ((const int4*)idx)[i4];
            if (v.x >= 0 && v.x < OPT) atomicAdd(&h[v.x], 1);
            if (v.y >= 0 && v.y < OPT) atomicAdd(&h[v.y], 1);
            if (v.z >= 0 && v.z < OPT) atomicAdd(&h[v.z], 1);
            if (v.w >= 0 && v.w < OPT) atomicAdd(&h[v.w], 1);
        } else {
            for (int i = i4 * 4; i < min(i4 * 4 + 4, B); i++) {
                int e = idx[i];
                if (e >= 0 && e < OPT) atomicAdd(&h[e], 1);
            }
        }
        __syncthreads();
        if (t < OPT) g_blockhist[b][t] = h[t];
    } else {
        // flat 8-float chunks over x then w
        int nxc = B * DIN / 8;
        int nwc = OPT * DIN * DOUT / 8;
        int cb = b - HBLK;
        int stride = (K1_BLOCKS - HBLK) * 256;
        for (int i = cb * 256 + t; i < nxc + nwc; i += stride) {
            const float* src;
            __nv_bfloat16 *dh, *dl;
            if (i < nxc) {
                src = x + (size_t)i * 8;
                dh = g_xhi + (size_t)i * 8;
                dl = g_xlo + (size_t)i * 8;
            } else {
                size_t j = (size_t)(i - nxc) * 8;
                src = w + j;
                dh = g_whi + j;
                dl = g_wlo + j;
            }
            float4 v0 = *(const float4*)(src);
            float4 v1 = *(const float4*)(src + 4);
            float vv[8] = {v0.x, v0.y, v0.z, v0.w, v1.x, v1.y, v1.z, v1.w};
            uint4 ph4, pl4;
            split8(vv, ph4, pl4);
            *(uint4*)dh = ph4;
            *(uint4*)dl = pl4;
        }
    }
}

__global__ void scan_kernel(int B) {
    __shared__ int tot[OPT];
    __shared__ int off[OPT];
    __shared__ int toff[OPT];
    int e = threadIdx.x;  // 64 threads
    int nblk = (B + 1023) / 1024;
    int s = 0;
    for (int b = 0; b < nblk; b++) s += g_blockhist[b][e];
    tot[e] = s;
    __syncthreads();
    if (e == 0) {
        int acc = 0, tacc = 0;
        for (int i = 0; i < OPT; i++) {
            off[i] = acc; acc += tot[i];
            toff[i] = tacc; tacc += (tot[i] + TILE_M - 1) / TILE_M;
        }
        g_ntiles = tacc;
    }
    __syncthreads();
    int run = off[e];
    for (int b = 0; b < nblk; b++) { g_blockbase[b][e] = run; run += g_blockhist[b][e]; }
    g_expert_end[e] = off[e] + tot[e];
    int nt = (tot[e] + TILE_M - 1) / TILE_M;
    for (int i = 0; i < nt; i++) {
        g_tile_e[toff[e] + i] = e;
        g_tile_m0[toff[e] + i] = off[e] + i * TILE_M;
    }
}

__global__ void scatter_kernel(const int* __restrict__ idx, int B) {
    __shared__ int cur[OPT];
    int t = threadIdx.x;
    if (t < OPT) cur[t] = 0;
    __syncthreads();
    int i4 = blockIdx.x * 256 + t;
    if (i4 * 4 + 3 < B) {
        int4 v = ((const int4*)idx)[i4];
        int es[4] = {v.x, v.y, v.z, v.w};
        #pragma unroll
        for (int j = 0; j < 4; j++) {
            int e = es[j];
            if (e >= 0 && e < OPT) {
                int r = atomicAdd(&cur[e], 1);
                g_rowids[g_blockbase[blockIdx.x][e] + r] = i4 * 4 + j;
            }
        }
    } else {
        for (int i = i4 * 4; i < min(i4 * 4 + 4, B); i++) {
            int e = idx[i];
            if (e >= 0 && e < OPT) {
                int r = atomicAdd(&cur[e], 1);
                g_rowids[g_blockbase[blockIdx.x][e] + r] = i;
            }
        }
    }
}

// ---------------- Compute: bf16 mma.sync, cp.async staging of pre-split data ----
// Tile 64(M) x 128(N) x 128(K). 8 warps 2x4. 2 blocks/SM.

#define LDA 136
#define SA_HI 0
#define SA_LO (TILE_M * LDA * 2)                      // 17408
#define SB_HI (2 * TILE_M * LDA * 2)                  // 34816
#define SB_LO (2 * TILE_M * LDA * 2 + DIN * LDA * 2)  // 69632
#define SROW  (2 * TILE_M * LDA * 2 + 2 * DIN * LDA * 2)  // 104448
#define SBIAS (SROW + 256)
#define SMEM_BYTES (SBIAS + 512)                      // 105216
#define NT 256

__device__ __forceinline__ uint32_t smem_u32(const void* p) {
    uint32_t a;
    asm("{ .reg .u64 tmp; cvta.to.shared.u64 tmp, %1; cvt.u32.u64 %0, tmp; }"
        : "=r"(a) : "l"(p));
    return a;
}

__device__ __forceinline__ void cp16(uint32_t dst, const void* src) {
    asm volatile("cp.async.cg.shared.global [%0], [%1], 16;"
                 :: "r"(dst), "l"(src) : "memory");
}

__device__ __forceinline__ void ldsm_x4(uint32_t* r, uint32_t addr) {
    asm volatile("ldmatrix.sync.aligned.m8n8.x4.shared.b16 {%0,%1,%2,%3}, [%4];"
        : "=r"(r[0]), "=r"(r[1]), "=r"(r[2]), "=r"(r[3]) : "r"(addr));
}

__device__ __forceinline__ void ldsm_x4t(uint32_t* r, uint32_t addr) {
    asm volatile("ldmatrix.sync.aligned.m8n8.x4.trans.shared.b16 {%0,%1,%2,%3}, [%4];"
        : "=r"(r[0]), "=r"(r[1]), "=r"(r[2]), "=r"(r[3]) : "r"(addr));
}

__device__ __forceinline__ void mma_bf16(float* c, const uint32_t* a, const uint32_t* b) {
    asm volatile(
        "mma.sync.aligned.m16n8k16.row.col.f32.bf16.bf16.f32 "
        "{%0,%1,%2,%3}, {%4,%5,%6,%7}, {%8,%9}, {%0,%1,%2,%3};"
        : "+f"(c[0]), "+f"(c[1]), "+f"(c[2]), "+f"(c[3])
        : "r"(a[0]), "r"(a[1]), "r"(a[2]), "r"(a[3]), "r"(b[0]), "r"(b[1]));
}

__global__ __launch_bounds__(NT, 2)
void mm_kernel(const float* __restrict__ bias, float* __restrict__ out) {
    int tile = blockIdx.x;
    if (tile >= g_ntiles) return;
    int e = g_tile_e[tile];
    int m0 = g_tile_m0[tile];
    int mcnt = min(TILE_M, g_expert_end[e] - m0);

    extern __shared__ char smem[];
    uint32_t sb = smem_u32(smem);
    int t = threadIdx.x;
    int wid = t >> 5;
    int lane = t & 31;

    int* srow = (int*)(smem + SROW);
    float* sbias = (float*)(smem + SBIAS);

    if (t < TILE_M) srow[t] = g_rowids[m0 + min(t, mcnt - 1)];
    if (t >= 64 && t < 64 + DOUT) sbias[t - 64] = bias[(size_t)e * DOUT + t - 64];

    // ---- Stage A via cp.async: 64 rows x 16 chunks (hi) + same (lo) ----
    // i in [0, 1024): m = i>>4, c = i&15
    #pragma unroll
    for (int i = t; i < TILE_M * 16; i += NT) {
        int m = i >> 4;
        int c = i & 15;
        int gr = g_rowids[m0 + min(m, mcnt - 1)];
        uint32_t doff = (uint32_t)(m * LDA + c * 8) * 2;
        const __nv_bfloat16* sh = g_xhi + (size_t)gr * DIN + c * 8;
        const __nv_bfloat16* sl = g_xlo + (size_t)gr * DIN + c * 8;
        cp16(sb + SA_HI + doff, sh);
        cp16(sb + SA_LO + doff, sl);
    }
    // ---- Stage B via cp.async: 128 rows x 16 chunks (hi+lo) ----
    #pragma unroll
    for (int i = t; i < DIN * 16; i += NT) {
        int k = i >> 4;
        int c = i & 15;
        uint32_t doff = (uint32_t)(k * LDA + c * 8) * 2;
        size_t soff = (size_t)e * DIN * DOUT + (size_t)k * DOUT + c * 8;
        cp16(sb + SB_HI + doff, g_whi + soff);
        cp16(sb + SB_LO + doff, g_wlo + soff);
    }
    asm volatile("cp.async.commit_group;" ::: "memory");
    asm volatile("cp.async.wait_group 0;" ::: "memory");
    __syncthreads();

    // ---- MMA mainloop: warp = (warp_m, warp_n), M32 x N32 ----
    int warp_m = wid & 1;
    int warp_n = wid >> 1;

    float acc[2][4][4];
    #pragma unroll
    for (int mt = 0; mt < 2; mt++)
        #pragma unroll
        for (int nt = 0; nt < 4; nt++)
            #pragma unroll
            for (int j = 0; j < 4; j++) acc[mt][nt][j] = 0.0f;

    int a_r = warp_m * 32 + (lane & 15);
    int a_c8 = (lane >> 4) << 3;
    int b_rk = (lane & 7) + (((lane >> 3) & 1) << 3);
    int b_c8 = (lane >> 4) << 3;

    #pragma unroll
    for (int ks = 0; ks < 8; ks++) {
        int k0 = ks * 16;
        uint32_t Ah[2][4], Al[2][4];
        #pragma unroll
        for (int mt = 0; mt < 2; mt++) {
            uint32_t off = (uint32_t)((a_r + mt * 16) * LDA + k0 + a_c8) * 2;
            ldsm_x4(Ah[mt], sb + SA_HI + off);
            ldsm_x4(Al[mt], sb + SA_LO + off);
        }
        #pragma unroll
        for (int np = 0; np < 2; np++) {
            int n0 = warp_n * 32 + np * 16;
            uint32_t boff = (uint32_t)((k0 + b_rk) * LDA + n0 + b_c8) * 2;
            uint32_t Bh[4], Bl[4];
            ldsm_x4t(Bh, sb + SB_HI + boff);
            ldsm_x4t(Bl, sb + SB_LO + boff);
            #pragma unroll
            for (int mt = 0; mt < 2; mt++) {
                mma_bf16(acc[mt][2 * np + 0], Ah[mt], Bh + 0);
                mma_bf16(acc[mt][2 * np + 1], Ah[mt], Bh + 2);
                mma_bf16(acc[mt][2 * np + 0], Ah[mt], Bl + 0);
                mma_bf16(acc[mt][2 * np + 1], Ah[mt], Bl + 2);
                mma_bf16(acc[mt][2 * np + 0], Al[mt], Bh + 0);
                mma_bf16(acc[mt][2 * np + 1], Al[mt], Bh + 2);
            }
        }
    }

    // ---- Epilogue: bias + scatter to out rows ----
    int g4 = lane >> 2;
    int t4 = lane & 3;
    #pragma unroll
    for (int mt = 0; mt < 2; mt++) {
        #pragma unroll
        for (int half = 0; half < 2; half++) {
            int m = warp_m * 32 + mt * 16 + half * 8 + g4;
            if (m < mcnt) {
                int gr = srow[m];
                float* orow = out + (size_t)gr * DOUT;
                #pragma unroll
                for (int nt = 0; nt < 4; nt++) {
                    int c = warp_n * 32 + nt * 8 + t4 * 2;
                    float2 v;
                    v.x = acc[mt][nt][half * 2 + 0] + sbias[c];
                    v.y = acc[mt][nt][half * 2 + 1] + sbias[c + 1];
                    *(float2*)(orow + c) = v;
                }
            }
        }
    }
}

extern "C" void kernel_launch(void* const* d_in, const int* in_sizes, int n_in,
                              void* d_out, int out_size) {
    const float* x = (const float*)d_in[0];
    const float* w = (const float*)d_in[1];
    const float* b = (const float*)d_in[2];
    const int* idx = (const int*)d_in[3];   // JAX x64-disabled: indices arrive int32
    float* out = (float*)d_out;
    int B = in_sizes[3];
    if (B > MAX_B) B = MAX_B;

    cudaFuncSetAttribute(mm_kernel, cudaFuncAttributeMaxDynamicSharedMemorySize,
                         SMEM_BYTES);

    int nblk = (B + 1023) / 1024;   // <= HBLK
    hist_convert_kernel<<<K1_BLOCKS, 256>>>(idx, x, w, B);
    scan_kernel<<<1, 64>>>(B);
    scatter_kernel<<<nblk, 256>>>(idx, B);
    mm_kernel<<<MAX_TILES, NT, SMEM_BYTES>>>(b, out);
}

// round 12
// speedup vs baseline: 1.3544x; 1.0127x over previous
#include <cuda_runtime.h>
#include <cuda_bf16.h>
#include <cstdint>

#define OPT 64
#define DIN 128
#define DOUT 128
#define TILE_M 64
#define MAX_B 16384
#define HBLK 16
#define MAX_TILES (MAX_B / TILE_M + OPT)      // 320

// ---- scratch (device allocation banned) ----
__device__ int g_blockhist[HBLK][OPT];
__device__ int g_blockbase[HBLK][OPT];
__device__ int g_expert_end[OPT];
__device__ int g_rowids[MAX_B];
__device__ int g_ntiles;
__device__ int g_tile_e[MAX_TILES];
__device__ int g_tile_m0[MAX_TILES];
// pre-split bf16 operands
__device__ __align__(16) __nv_bfloat16 g_xhi[MAX_B * DIN];
__device__ __align__(16) __nv_bfloat16 g_xlo[MAX_B * DIN];
__device__ __align__(16) __nv_bfloat16 g_whi[OPT * DIN * DOUT];
__device__ __align__(16) __nv_bfloat16 g_wlo[OPT * DIN * DOUT];

__device__ __forceinline__ uint32_t pack_bf2(__nv_bfloat16 lo, __nv_bfloat16 hi) {
    return ((uint32_t)__bfloat16_as_ushort(hi) << 16) | __bfloat16_as_ushort(lo);
}

__device__ __forceinline__ void split8(const float* vv, uint4& ph4, uint4& pl4) {
    uint32_t ph[4], pl[4];
    #pragma unroll
    for (int j = 0; j < 4; j++) {
        __nv_bfloat16 h0 = __float2bfloat16_rn(vv[2 * j]);
        __nv_bfloat16 h1 = __float2bfloat16_rn(vv[2 * j + 1]);
        __nv_bfloat16 l0 = __float2bfloat16_rn(vv[2 * j] - __bfloat162float(h0));
        __nv_bfloat16 l1 = __float2bfloat16_rn(vv[2 * j + 1] - __bfloat162float(h1));
        ph[j] = pack_bf2(h0, h1);
        pl[j] = pack_bf2(l0, l1);
    }
    ph4 = make_uint4(ph[0], ph[1], ph[2], ph[3]);
    pl4 = make_uint4(pl[0], pl[1], pl[2], pl[3]);
}

// generic flat converter: chunk i = 8 consecutive floats
__device__ __forceinline__ void convert_range(const float* __restrict__ src,
                                              __nv_bfloat16* __restrict__ dhi,
                                              __nv_bfloat16* __restrict__ dlo,
                                              int nchunks, int start, int stride) {
    for (int i = start; i < nchunks; i += stride) {
        const float* s = src + (size_t)i * 8;
        float4 v0 = *(const float4*)(s);
        float4 v1 = *(const float4*)(s + 4);
        float vv[8] = {v0.x, v0.y, v0.z, v0.w, v1.x, v1.y, v1.z, v1.w};
        uint4 ph4, pl4;
        split8(vv, ph4, pl4);
        *(uint4*)(dhi + (size_t)i * 8) = ph4;
        *(uint4*)(dlo + (size_t)i * 8) = pl4;
    }
}

// ---------------- K1: hist (blocks 0..15) + convert x (blocks 16..255) ----------------

#define K1_BLOCKS 256

__global__ void hist_convx_kernel(const int* __restrict__ idx,
                                  const float* __restrict__ x, int B) {
    int t = threadIdx.x;
    int b = blockIdx.x;
    if (b < HBLK) {
        __shared__ int h[OPT];
        if (t < OPT) h[t] = 0;
        __syncthreads();
        int i4 = b * 256 + t;
        if (i4 * 4 + 3 < B) {
            int4 v = ((const int4*)idx)[i4];
            if (v.x >= 0 && v.x < OPT) atomicAdd(&h[v.x], 1);
            if (v.y >= 0 && v.y < OPT) atomicAdd(&h[v.y], 1);
            if (v.z >= 0 && v.z < OPT) atomicAdd(&h[v.z], 1);
            if (v.w >= 0 && v.w < OPT) atomicAdd(&h[v.w], 1);
        } else {
            for (int i = i4 * 4; i < min(i4 * 4 + 4, B); i++) {
                int e = idx[i];
                if (e >= 0 && e < OPT) atomicAdd(&h[e], 1);
            }
        }
        __syncthreads();
        if (t < OPT) g_blockhist[b][t] = h[t];
    } else {
        int nxc = B * DIN / 8;
        convert_range(x, g_xhi, g_xlo, nxc,
                      (b - HBLK) * 256 + t, (K1_BLOCKS - HBLK) * 256);
    }
}

__global__ void scan_kernel(int B) {
    __shared__ int tot[OPT];
    __shared__ int off[OPT];
    __shared__ int toff[OPT];
    int e = threadIdx.x;  // 64 threads
    int nblk = (B + 1023) / 1024;
    int s = 0;
    for (int b = 0; b < nblk; b++) s += g_blockhist[b][e];
    tot[e] = s;
    __syncthreads();
    if (e == 0) {
        int acc = 0, tacc = 0;
        for (int i = 0; i < OPT; i++) {
            off[i] = acc; acc += tot[i];
            toff[i] = tacc; tacc += (tot[i] + TILE_M - 1) / TILE_M;
        }
        g_ntiles = tacc;
    }
    __syncthreads();
    int run = off[e];
    for (int b = 0; b < nblk; b++) { g_blockbase[b][e] = run; run += g_blockhist[b][e]; }
    g_expert_end[e] = off[e] + tot[e];
    int nt = (tot[e] + TILE_M - 1) / TILE_M;
    for (int i = 0; i < nt; i++) {
        g_tile_e[toff[e] + i] = e;
        g_tile_m0[toff[e] + i] = off[e] + i * TILE_M;
    }
}

// ---------------- K3: scatter (blocks 0..15) + convert w (blocks 16..255) --------------

#define K3_BLOCKS 256

__global__ void scatter_convw_kernel(const int* __restrict__ idx,
                                     const float* __restrict__ w, int B) {
    int t = threadIdx.x;
    int b = blockIdx.x;
    if (b < HBLK) {
        __shared__ int cur[OPT];
        if (t < OPT) cur[t] = 0;
        __syncthreads();
        int i4 = b * 256 + t;
        if (i4 * 4 + 3 < B) {
            int4 v = ((const int4*)idx)[i4];
            int es[4] = {v.x, v.y, v.z, v.w};
            #pragma unroll
            for (int j = 0; j < 4; j++) {
                int e = es[j];
                if (e >= 0 && e < OPT) {
                    int r = atomicAdd(&cur[e], 1);
                    g_rowids[g_blockbase[b][e] + r] = i4 * 4 + j;
                }
            }
        } else {
            for (int i = i4 * 4; i < min(i4 * 4 + 4, B); i++) {
                int e = idx[i];
                if (e >= 0 && e < OPT) {
                    int r = atomicAdd(&cur[e], 1);
                    g_rowids[g_blockbase[b][e] + r] = i;
                }
            }
        }
    } else {
        int nwc = OPT * DIN * DOUT / 8;
        convert_range(w, g_whi, g_wlo, nwc,
                      (b - HBLK) * 256 + t, (K3_BLOCKS - HBLK) * 256);
    }
}

// ---------------- Compute: bf16 mma.sync, cp.async staging of pre-split data ----
// Tile 64(M) x 128(N) x 128(K). 8 warps 2x4. 2 blocks/SM.

#define LDA 136
#define SA_HI 0
#define SA_LO (TILE_M * LDA * 2)                      // 17408
#define SB_HI (2 * TILE_M * LDA * 2)                  // 34816
#define SB_LO (2 * TILE_M * LDA * 2 + DIN * LDA * 2)  // 69632
#define SROW  (2 * TILE_M * LDA * 2 + 2 * DIN * LDA * 2)  // 104448
#define SBIAS (SROW + 256)
#define SMEM_BYTES (SBIAS + 512)                      // 105216
#define NT 256

__device__ __forceinline__ uint32_t smem_u32(const void* p) {
    uint32_t a;
    asm("{ .reg .u64 tmp; cvta.to.shared.u64 tmp, %1; cvt.u32.u64 %0, tmp; }"
        : "=r"(a) : "l"(p));
    return a;
}

__device__ __forceinline__ void cp16(uint32_t dst, const void* src) {
    asm volatile("cp.async.cg.shared.global [%0], [%1], 16;"
                 :: "r"(dst), "l"(src) : "memory");
}

__device__ __forceinline__ void ldsm_x4(uint32_t* r, uint32_t addr) {
    asm volatile("ldmatrix.sync.aligned.m8n8.x4.shared.b16 {%0,%1,%2,%3}, [%4];"
        : "=r"(r[0]), "=r"(r[1]), "=r"(r[2]), "=r"(r[3]) : "r"(addr));
}

__device__ __forceinline__ void ldsm_x4t(uint32_t* r, uint32_t addr) {
    asm volatile("ldmatrix.sync.aligned.m8n8.x4.trans.shared.b16 {%0,%1,%2,%3}, [%4];"
        : "=r"(r[0]), "=r"(r[1]), "=r"(r[2]), "=r"(r[3]) : "r"(addr));
}

__device__ __forceinline__ void mma_bf16(float* c, const uint32_t* a, const uint32_t* b) {
    asm volatile(
        "mma.sync.aligned.m16n8k16.row.col.f32.bf16.bf16.f32 "
        "{%0,%1,%2,%3}, {%4,%5,%6,%7}, {%8,%9}, {%0,%1,%2,%3};"
        : "+f"(c[0]), "+f"(c[1]), "+f"(c[2]), "+f"(c[3])
        : "r"(a[0]), "r"(a[1]), "r"(a[2]), "r"(a[3]), "r"(b[0]), "r"(b[1]));
}

__global__ __launch_bounds__(NT, 2)
void mm_kernel(const float* __restrict__ bias, float* __restrict__ out) {
    int tile = blockIdx.x;
    if (tile >= g_ntiles) return;
    int e = g_tile_e[tile];
    int m0 = g_tile_m0[tile];
    int mcnt = min(TILE_M, g_expert_end[e] - m0);

    extern __shared__ char smem[];
    uint32_t sb = smem_u32(smem);
    int t = threadIdx.x;
    int wid = t >> 5;
    int lane = t & 31;

    int* srow = (int*)(smem + SROW);
    float* sbias = (float*)(smem + SBIAS);

    if (t < TILE_M) srow[t] = g_rowids[m0 + min(t, mcnt - 1)];
    if (t >= 64 && t < 64 + DOUT) sbias[t - 64] = bias[(size_t)e * DOUT + t - 64];

    // ---- Stage A via cp.async: 64 rows x 16 chunks (hi+lo) ----
    #pragma unroll
    for (int i = t; i < TILE_M * 16; i += NT) {
        int m = i >> 4;
        int c = i & 15;
        int gr = g_rowids[m0 + min(m, mcnt - 1)];
        uint32_t doff = (uint32_t)(m * LDA + c * 8) * 2;
        const __nv_bfloat16* sh = g_xhi + (size_t)gr * DIN + c * 8;
        const __nv_bfloat16* sl = g_xlo + (size_t)gr * DIN + c * 8;
        cp16(sb + SA_HI + doff, sh);
        cp16(sb + SA_LO + doff, sl);
    }
    // ---- Stage B via cp.async: 128 rows x 16 chunks (hi+lo) ----
    #pragma unroll
    for (int i = t; i < DIN * 16; i += NT) {
        int k = i >> 4;
        int c = i & 15;
        uint32_t doff = (uint32_t)(k * LDA + c * 8) * 2;
        size_t soff = (size_t)e * DIN * DOUT + (size_t)k * DOUT + c * 8;
        cp16(sb + SB_HI + doff, g_whi + soff);
        cp16(sb + SB_LO + doff, g_wlo + soff);
    }
    asm volatile("cp.async.commit_group;" ::: "memory");
    asm volatile("cp.async.wait_group 0;" ::: "memory");
    __syncthreads();

    // ---- MMA mainloop: warp = (warp_m, warp_n), M32 x N32 ----
    int warp_m = wid & 1;
    int warp_n = wid >> 1;

    float acc[2][4][4];
    #pragma unroll
    for (int mt = 0; mt < 2; mt++)
        #pragma unroll
        for (int nt = 0; nt < 4; nt++)
            #pragma unroll
            for (int j = 0; j < 4; j++) acc[mt][nt][j] = 0.0f;

    int a_r = warp_m * 32 + (lane & 15);
    int a_c8 = (lane >> 4) << 3;
    int b_rk = (lane & 7) + (((lane >> 3) & 1) << 3);
    int b_c8 = (lane >> 4) << 3;

    #pragma unroll
    for (int ks = 0; ks < 8; ks++) {
        int k0 = ks * 16;
        uint32_t Ah[2][4], Al[2][4];
        #pragma unroll
        for (int mt = 0; mt < 2; mt++) {
            uint32_t off = (uint32_t)((a_r + mt * 16) * LDA + k0 + a_c8) * 2;
            ldsm_x4(Ah[mt], sb + SA_HI + off);
            ldsm_x4(Al[mt], sb + SA_LO + off);
        }
        #pragma unroll
        for (int np = 0; np < 2; np++) {
            int n0 = warp_n * 32 + np * 16;
            uint32_t boff = (uint32_t)((k0 + b_rk) * LDA + n0 + b_c8) * 2;
            uint32_t Bh[4], Bl[4];
            ldsm_x4t(Bh, sb + SB_HI + boff);
            ldsm_x4t(Bl, sb + SB_LO + boff);
            #pragma unroll
            for (int mt = 0; mt < 2; mt++) {
                mma_bf16(acc[mt][2 * np + 0], Ah[mt], Bh + 0);
                mma_bf16(acc[mt][2 * np + 1], Ah[mt], Bh + 2);
                mma_bf16(acc[mt][2 * np + 0], Ah[mt], Bl + 0);
                mma_bf16(acc[mt][2 * np + 1], Ah[mt], Bl + 2);
                mma_bf16(acc[mt][2 * np + 0], Al[mt], Bh + 0);
                mma_bf16(acc[mt][2 * np + 1], Al[mt], Bh + 2);
            }
        }
    }

    // ---- Epilogue: bias + scatter to out rows ----
    int g4 = lane >> 2;
    int t4 = lane & 3;
    #pragma unroll
    for (int mt = 0; mt < 2; mt++) {
        #pragma unroll
        for (int half = 0; half < 2; half++) {
            int m = warp_m * 32 + mt * 16 + half * 8 + g4;
            if (m < mcnt) {
                int gr = srow[m];
                float* orow = out + (size_t)gr * DOUT;
                #pragma unroll
                for (int nt = 0; nt < 4; nt++) {
                    int c = warp_n * 32 + nt * 8 + t4 * 2;
                    float2 v;
                    v.x = acc[mt][nt][half * 2 + 0] + sbias[c];
                    v.y = acc[mt][nt][half * 2 + 1] + sbias[c + 1];
                    *(float2*)(orow + c) = v;
                }
            }
        }
    }
}

extern "C" void kernel_launch(void* const* d_in, const int* in_sizes, int n_in,
                              void* d_out, int out_size) {
    const float* x = (const float*)d_in[0];
    const float* w = (const float*)d_in[1];
    const float* b = (const float*)d_in[2];
    const int* idx = (const int*)d_in[3];   // JAX x64-disabled: indices arrive int32
    float* out = (float*)d_out;
    int B = in_sizes[3];
    if (B > MAX_B) B = MAX_B;

    cudaFuncSetAttribute(mm_kernel, cudaFuncAttributeMaxDynamicSharedMemorySize,
                         SMEM_BYTES);

    hist_convx_kernel<<<K1_BLOCKS, 256>>>(idx, x, B);
    scan_kernel<<<1, 64>>>(B);
    scatter_convw_kernel<<<K3_BLOCKS, 256>>>(idx, w, B);
    mm_kernel<<<MAX_TILES, NT, SMEM_BYTES>>>(b, out);
}

// round 13
// speedup vs baseline: 1.4884x; 1.0989x over previous
#include <cuda_runtime.h>
#include <cuda_bf16.h>
#include <cstdint>

#define OPT 64
#define DIN 128
#define DOUT 128
#define TILE_M 64
#define MAX_B 16384
#define HBLK 16
#define MAX_TILES (MAX_B / TILE_M + OPT)      // 320

// ---- scratch (device allocation banned) ----
__device__ int g_blockhist[HBLK][OPT];
__device__ int g_rowids[MAX_B];
__device__ int g_scatter_done;
// pre-split bf16 operands
__device__ __align__(16) __nv_bfloat16 g_xhi[MAX_B * DIN];
__device__ __align__(16) __nv_bfloat16 g_xlo[MAX_B * DIN];
__device__ __align__(16) __nv_bfloat16 g_whi[OPT * DIN * DOUT];
__device__ __align__(16) __nv_bfloat16 g_wlo[OPT * DIN * DOUT];

__device__ __forceinline__ uint32_t pack_bf2(__nv_bfloat16 lo, __nv_bfloat16 hi) {
    return ((uint32_t)__bfloat16_as_ushort(hi) << 16) | __bfloat16_as_ushort(lo);
}

__device__ __forceinline__ void split8(const float* vv, uint4& ph4, uint4& pl4) {
    uint32_t ph[4], pl[4];
    #pragma unroll
    for (int j = 0; j < 4; j++) {
        __nv_bfloat16 h0 = __float2bfloat16_rn(vv[2 * j]);
        __nv_bfloat16 h1 = __float2bfloat16_rn(vv[2 * j + 1]);
        __nv_bfloat16 l0 = __float2bfloat16_rn(vv[2 * j] - __bfloat162float(h0));
        __nv_bfloat16 l1 = __float2bfloat16_rn(vv[2 * j + 1] - __bfloat162float(h1));
        ph[j] = pack_bf2(h0, h1);
        pl[j] = pack_bf2(l0, l1);
    }
    ph4 = make_uint4(ph[0], ph[1], ph[2], ph[3]);
    pl4 = make_uint4(pl[0], pl[1], pl[2], pl[3]);
}

__device__ __forceinline__ void convert_range(const float* __restrict__ src,
                                              __nv_bfloat16* __restrict__ dhi,
                                              __nv_bfloat16* __restrict__ dlo,
                                              int nchunks, int start, int stride) {
    for (int i = start; i < nchunks; i += stride) {
        const float* s = src + (size_t)i * 8;
        float4 v0 = *(const float4*)(s);
        float4 v1 = *(const float4*)(s + 4);
        float vv[8] = {v0.x, v0.y, v0.z, v0.w, v1.x, v1.y, v1.z, v1.w};
        uint4 ph4, pl4;
        split8(vv, ph4, pl4);
        *(uint4*)(dhi + (size_t)i * 8) = ph4;
        *(uint4*)(dlo + (size_t)i * 8) = pl4;
    }
}

// ---------------- K1: hist (blocks 0..15) + convert x,w (blocks 16..255) ------------

#define K1_BLOCKS 256

__global__ void hist_conv_kernel(const int* __restrict__ idx,
                                 const float* __restrict__ x,
                                 const float* __restrict__ w, int B) {
    int t = threadIdx.x;
    int b = blockIdx.x;
    if (b == 0 && t == 0) g_scatter_done = 0;   // reset for this replay
    if (b < HBLK) {
        __shared__ int h[OPT];
        if (t < OPT) h[t] = 0;
        __syncthreads();
        int i4 = b * 256 + t;
        if (i4 * 4 + 3 < B) {
            int4 v = ((const int4*)idx)[i4];
            if (v.x >= 0 && v.x < OPT) atomicAdd(&h[v.x], 1);
            if (v.y >= 0 && v.y < OPT) atomicAdd(&h[v.y], 1);
            if (v.z >= 0 && v.z < OPT) atomicAdd(&h[v.z], 1);
            if (v.w >= 0 && v.w < OPT) atomicAdd(&h[v.w], 1);
        } else {
            for (int i = i4 * 4; i < min(i4 * 4 + 4, B); i++) {
                int e = idx[i];
                if (e >= 0 && e < OPT) atomicAdd(&h[e], 1);
            }
        }
        __syncthreads();
        if (t < OPT) g_blockhist[b][t] = h[t];
    } else {
        int nxc = B * DIN / 8;
        int nwc = OPT * DIN * DOUT / 8;
        int start = (b - HBLK) * 256 + t;
        int stride = (K1_BLOCKS - HBLK) * 256;
        for (int i = start; i < nxc + nwc; i += stride) {
            if (i < nxc) {
                const float* s = x + (size_t)i * 8;
                float4 v0 = *(const float4*)(s);
                float4 v1 = *(const float4*)(s + 4);
                float vv[8] = {v0.x, v0.y, v0.z, v0.w, v1.x, v1.y, v1.z, v1.w};
                uint4 ph4, pl4;
                split8(vv, ph4, pl4);
                *(uint4*)(g_xhi + (size_t)i * 8) = ph4;
                *(uint4*)(g_xlo + (size_t)i * 8) = pl4;
            } else {
                size_t j = (size_t)(i - nxc) * 8;
                const float* s = w + j;
                float4 v0 = *(const float4*)(s);
                float4 v1 = *(const float4*)(s + 4);
                float vv[8] = {v0.x, v0.y, v0.z, v0.w, v1.x, v1.y, v1.z, v1.w};
                uint4 ph4, pl4;
                split8(vv, ph4, pl4);
                *(uint4*)(g_whi + j) = ph4;
                *(uint4*)(g_wlo + j) = pl4;
            }
        }
    }
}

// ---------------- K2: fused scan + scatter + mm ----------------
// Tile 64(M) x 128(N) x 128(K). 8 warps 2x4. 2 blocks/SM.

#define LDA 136
#define SA_HI 0
#define SA_LO (TILE_M * LDA * 2)                      // 17408
#define SB_HI (2 * TILE_M * LDA * 2)                  // 34816
#define SB_LO (2 * TILE_M * LDA * 2 + DIN * LDA * 2)  // 69632
#define SROW  (2 * TILE_M * LDA * 2 + 2 * DIN * LDA * 2)  // 104448
#define SBIAS (SROW + 256)
#define SSCAN (SBIAS + 512)   // tot[64] | off[64] | meta[8] | cur[64]
#define SMEM_BYTES (SSCAN + 1024)                     // 106752
#define NT 256

__device__ __forceinline__ uint32_t smem_u32(const void* p) {
    uint32_t a;
    asm("{ .reg .u64 tmp; cvta.to.shared.u64 tmp, %1; cvt.u32.u64 %0, tmp; }"
        : "=r"(a) : "l"(p));
    return a;
}

__device__ __forceinline__ void cp16(uint32_t dst, const void* src) {
    asm volatile("cp.async.cg.shared.global [%0], [%1], 16;"
                 :: "r"(dst), "l"(src) : "memory");
}

__device__ __forceinline__ void ldsm_x4(uint32_t* r, uint32_t addr) {
    asm volatile("ldmatrix.sync.aligned.m8n8.x4.shared.b16 {%0,%1,%2,%3}, [%4];"
        : "=r"(r[0]), "=r"(r[1]), "=r"(r[2]), "=r"(r[3]) : "r"(addr));
}

__device__ __forceinline__ void ldsm_x4t(uint32_t* r, uint32_t addr) {
    asm volatile("ldmatrix.sync.aligned.m8n8.x4.trans.shared.b16 {%0,%1,%2,%3}, [%4];"
        : "=r"(r[0]), "=r"(r[1]), "=r"(r[2]), "=r"(r[3]) : "r"(addr));
}

__device__ __forceinline__ void mma_bf16(float* c, const uint32_t* a, const uint32_t* b) {
    asm volatile(
        "mma.sync.aligned.m16n8k16.row.col.f32.bf16.bf16.f32 "
        "{%0,%1,%2,%3}, {%4,%5,%6,%7}, {%8,%9}, {%0,%1,%2,%3};"
        : "+f"(c[0]), "+f"(c[1]), "+f"(c[2]), "+f"(c[3])
        : "r"(a[0]), "r"(a[1]), "r"(a[2]), "r"(a[3]), "r"(b[0]), "r"(b[1]));
}

__global__ __launch_bounds__(NT, 2)
void mm_fused_kernel(const int* __restrict__ idx, const float* __restrict__ bias,
                     float* __restrict__ out, int B) {
    extern __shared__ char smem[];
    uint32_t sb = smem_u32(smem);
    int t = threadIdx.x;
    int b = blockIdx.x;
    int wid = t >> 5;
    int lane = t & 31;

    int* tot  = (int*)(smem + SSCAN);
    int* off  = tot + 64;
    int* meta = off + 64;
    int* cur  = meta + 8;

    // ---- redundant scan (every block) ----
    if (t < OPT) {
        int s = 0;
        #pragma unroll
        for (int bb = 0; bb < HBLK; bb++) s += g_blockhist[bb][t];
        tot[t] = s;
    }
    __syncthreads();
    if (t == 0) {
        int a = 0;
        for (int e2 = 0; e2 < OPT; e2++) { off[e2] = a; a += tot[e2]; }
    }
    __syncthreads();

    // ---- scatter duty (blocks 0..15) ----
    if (b < HBLK) {
        if (t < OPT) {
            int pre = off[t];
            for (int bb = 0; bb < b; bb++) pre += g_blockhist[bb][t];
            cur[t] = pre;
        }
        __syncthreads();
        int i4 = b * 256 + t;
        if (i4 * 4 + 3 < B) {
            int4 v = ((const int4*)idx)[i4];
            int es[4] = {v.x, v.y, v.z, v.w};
            #pragma unroll
            for (int j = 0; j < 4; j++) {
                int e2 = es[j];
                if (e2 >= 0 && e2 < OPT) {
                    int r = atomicAdd(&cur[e2], 1);
                    g_rowids[r] = i4 * 4 + j;
                }
            }
        } else {
            for (int i = i4 * 4; i < min(i4 * 4 + 4, B); i++) {
                int e2 = idx[i];
                if (e2 >= 0 && e2 < OPT) {
                    int r = atomicAdd(&cur[e2], 1);
                    g_rowids[r] = i;
                }
            }
        }
        __threadfence();
        __syncthreads();
        if (t == 0) atomicAdd(&g_scatter_done, 1);
    }

    // ---- my tile ----
    if (t == 0) {
        int cum = 0, fe = -1, fm0 = 0;
        for (int e2 = 0; e2 < OPT; e2++) {
            int nt2 = (tot[e2] + TILE_M - 1) >> 6;
            if (fe < 0 && b < cum + nt2) { fe = e2; fm0 = off[e2] + (b - cum) * TILE_M; }
            cum += nt2;
        }
        meta[0] = fe; meta[1] = fm0;
    }
    __syncthreads();
    int e = meta[0];
    if (e < 0) return;
    int m0 = meta[1];
    int mcnt = min(TILE_M, off[e] + tot[e] - m0);

    // ---- Stage B immediately via cp.async (independent of scatter) ----
    #pragma unroll
    for (int i = t; i < DIN * 16; i += NT) {
        int k = i >> 4;
        int c = i & 15;
        uint32_t doff = (uint32_t)(k * LDA + c * 8) * 2;
        size_t soff = (size_t)e * DIN * DOUT + (size_t)k * DOUT + c * 8;
        cp16(sb + SB_HI + doff, g_whi + soff);
        cp16(sb + SB_LO + doff, g_wlo + soff);
    }
    asm volatile("cp.async.commit_group;" ::: "memory");

    float* sbias = (float*)(smem + SBIAS);
    if (t >= 64 && t < 64 + DOUT) sbias[t - 64] = bias[(size_t)e * DOUT + t - 64];

    // ---- wait for scatter completion (B copy in flight meanwhile) ----
    if (t == 0) {
        int v;
        do {
            asm volatile("ld.global.acquire.gpu.b32 %0, [%1];"
                         : "=r"(v) : "l"(&g_scatter_done) : "memory");
        } while (v < HBLK);
    }
    __syncthreads();

    int* srow = (int*)(smem + SROW);
    if (t < TILE_M) srow[t] = g_rowids[m0 + min(t, mcnt - 1)];
    __syncthreads();

    // ---- Stage A via cp.async ----
    #pragma unroll
    for (int i = t; i < TILE_M * 16; i += NT) {
        int m = i >> 4;
        int c = i & 15;
        int gr = srow[m];
        uint32_t doff = (uint32_t)(m * LDA + c * 8) * 2;
        cp16(sb + SA_HI + doff, g_xhi + (size_t)gr * DIN + c * 8);
        cp16(sb + SA_LO + doff, g_xlo + (size_t)gr * DIN + c * 8);
    }
    asm volatile("cp.async.commit_group;" ::: "memory");
    asm volatile("cp.async.wait_group 0;" ::: "memory");
    __syncthreads();

    // ---- MMA mainloop (unchanged) ----
    int warp_m = wid & 1;
    int warp_n = wid >> 1;

    float acc[2][4][4];
    #pragma unroll
    for (int mt = 0; mt < 2; mt++)
        #pragma unroll
        for (int nt = 0; nt < 4; nt++)
            #pragma unroll
            for (int j = 0; j < 4; j++) acc[mt][nt][j] = 0.0f;

    int a_r = warp_m * 32 + (lane & 15);
    int a_c8 = (lane >> 4) << 3;
    int b_rk = (lane & 7) + (((lane >> 3) & 1) << 3);
    int b_c8 = (lane >> 4) << 3;

    #pragma unroll
    for (int ks = 0; ks < 8; ks++) {
        int k0 = ks * 16;
        uint32_t Ah[2][4], Al[2][4];
        #pragma unroll
        for (int mt = 0; mt < 2; mt++) {
            uint32_t aoff = (uint32_t)((a_r + mt * 16) * LDA + k0 + a_c8) * 2;
            ldsm_x4(Ah[mt], sb + SA_HI + aoff);
            ldsm_x4(Al[mt], sb + SA_LO + aoff);
        }
        #pragma unroll
        for (int np = 0; np < 2; np++) {
            int n0 = warp_n * 32 + np * 16;
            uint32_t boff = (uint32_t)((k0 + b_rk) * LDA + n0 + b_c8) * 2;
            uint32_t Bh[4], Bl[4];
            ldsm_x4t(Bh, sb + SB_HI + boff);
            ldsm_x4t(Bl, sb + SB_LO + boff);
            #pragma unroll
            for (int mt = 0; mt < 2; mt++) {
                mma_bf16(acc[mt][2 * np + 0], Ah[mt], Bh + 0);
                mma_bf16(acc[mt][2 * np + 1], Ah[mt], Bh + 2);
                mma_bf16(acc[mt][2 * np + 0], Ah[mt], Bl + 0);
                mma_bf16(acc[mt][2 * np + 1], Ah[mt], Bl + 2);
                mma_bf16(acc[mt][2 * np + 0], Al[mt], Bh + 0);
                mma_bf16(acc[mt][2 * np + 1], Al[mt], Bh + 2);
            }
        }
    }

    // ---- Epilogue: bias + scatter to out rows ----
    int g4 = lane >> 2;
    int t4 = lane & 3;
    #pragma unroll
    for (int mt = 0; mt < 2; mt++) {
        #pragma unroll
        for (int half = 0; half < 2; half++) {
            int m = warp_m * 32 + mt * 16 + half * 8 + g4;
            if (m < mcnt) {
                int gr = srow[m];
                float* orow = out + (size_t)gr * DOUT;
                #pragma unroll
                for (int nt = 0; nt < 4; nt++) {
                    int c = warp_n * 32 + nt * 8 + t4 * 2;
                    float2 v;
                    v.x = acc[mt][nt][half * 2 + 0] + sbias[c];
                    v.y = acc[mt][nt][half * 2 + 1] + sbias[c + 1];
                    *(float2*)(orow + c) = v;
                }
            }
        }
    }
}

extern "C" void kernel_launch(void* const* d_in, const int* in_sizes, int n_in,
                              void* d_out, int out_size) {
    const float* x = (const float*)d_in[0];
    const float* w = (const float*)d_in[1];
    const float* b = (const float*)d_in[2];
    const int* idx = (const int*)d_in[3];   // JAX x64-disabled: indices arrive int32
    float* out = (float*)d_out;
    int B = in_sizes[3];
    if (B > MAX_B) B = MAX_B;

    cudaFuncSetAttribute(mm_fused_kernel, cudaFuncAttributeMaxDynamicSharedMemorySize,
                         SMEM_BYTES);

    hist_conv_kernel<<<K1_BLOCKS, 256>>>(idx, x, w, B);
    mm_fused_kernel<<<MAX_TILES, NT, SMEM_BYTES>>>(idx, b, out, B);
}